// round 16
// baseline (speedup 1.0000x reference)
#include <cuda_runtime.h>

// WLC loss: fused 5-iter morphological recurrence, register-resident pred,
// packed f32x2 arithmetic. Warp = 128-px row band (32 lanes x 4 cols),
// thread owns R=7 rows; warp strips exchange edge rows via triple-slot smem
// (parities 0/1 + INIT). NT=512, 2 CTAs/SM @ 64 regs => 32 warps/SM.

#define IMG    4096
#define NT     512
#define WARPS  16
#define R      7
#define EXTX   128
#define TSX    112                 // gx0 = bx*112-8 => 16B-aligned
#define EXTY   (WARPS * R + 2)     // 114
#define TSY    (EXTY - 10)         // 104
#define GRIDX  37                  // ceil(4096/112)
#define GRIDY  40                  // ceil(4096/104)
#define NBLK   (GRIDX * GRIDY)     // 1480 = 5.0 waves of 296
#define CLOX   8                   // useful ext cols [8,120)
#define CHIX   120
#define CLOY   5                   // useful ext rows [5,109)
#define CHIY   (EXTY - 5)

#define GTN    (EXTY * EXTX)           // 14592 floats (gt/2)
#define ETSLOT (WARPS + 1)
#define ETN    (3 * ETSLOT * EXTX)     // 6528  (parity 0,1 + INIT=2)
#define EBN    (3 * WARPS * EXTX)      // 6144
#define SMEMB  ((GTN + ETN + EBN) * 4) // 109056 B (2 CTAs = 218KB <= 228KB)

typedef unsigned long long ull;

__device__ float    g_acc[2];   // zero-init; self-resets every launch
__device__ unsigned g_done;

__device__ __forceinline__ float tanha(float x) {
    float y; asm("tanh.approx.f32 %0, %1;" : "=f"(y) : "f"(x)); return y;
}
__device__ __forceinline__ ull pk2(float a, float b) {
    ull r; asm("mov.b64 %0, {%1, %2};" : "=l"(r) : "f"(a), "f"(b)); return r;
}
__device__ __forceinline__ void up2(ull v, float& a, float& b) {
    asm("mov.b64 {%0, %1}, %2;" : "=f"(a), "=f"(b) : "l"(v));
}
__device__ __forceinline__ ull add2(ull a, ull b) {
    ull r; asm("add.rn.f32x2 %0, %1, %2;" : "=l"(r) : "l"(a), "l"(b)); return r;
}
__device__ __forceinline__ ull fma2(ull a, ull b, ull c) {
    ull r; asm("fma.rn.f32x2 %0, %1, %2, %3;" : "=l"(r) : "l"(a), "l"(b), "l"(c));
    return r;
}

struct F2x2 { ull a, b; };   // (x,y),(z,w)

// horizontal 3-sums; lane-boundary values only pollute the halo-creep zone
__device__ __forceinline__ F2x2 hsum2(F2x2 v) {
    float x, y, z, w;
    up2(v.a, x, y); up2(v.b, z, w);
    float l = __shfl_up_sync(0xffffffffu, w, 1);
    float r = __shfl_down_sync(0xffffffffu, x, 1);
    float t1 = x + y, t2 = z + w;
    F2x2 h;
    h.a = pk2(l + t1, t1 + z);
    h.b = pk2(y + t2, t2 + r);
    return h;
}

__device__ __forceinline__ float4 ldrow(const float* __restrict__ p, int gy, int gx) {
    if (((unsigned)gy < (unsigned)IMG) && ((unsigned)gx <= (unsigned)(IMG - 4)))
        return *reinterpret_cast<const float4*>(p + (size_t)gy * IMG + gx);
    return make_float4(0.f, 0.f, 0.f, 0.f);
}
__device__ __forceinline__ float4 ld4s(const float* p) {
    return *reinterpret_cast<const float4*>(p);
}
__device__ __forceinline__ void st4s(float* p, float4 v) {
    *reinterpret_cast<float4*>(p) = v;
}

__global__ __launch_bounds__(NT, 2)
void wlc_main(const float* __restrict__ pred, const float* __restrict__ gt,
              float* __restrict__ out)
{
    extern __shared__ float sm[];
    float* gtb = sm;             // gt/2 tile [EXTY][EXTX]
    float* eT  = sm + GTN;       // [3][WARPS+1][EXTX]
    float* eB  = eT + ETN;       // [3][WARPS][EXTX]

    const int tid  = threadIdx.x;
    const int w    = tid >> 5;
    const int lane = tid & 31;
    const int col0 = 4 * lane;
    const int gx0  = blockIdx.x * TSX - CLOX;   // aligned to 4
    const int gy0  = blockIdx.y * TSY - CLOY;
    const int gxB  = gx0 + col0;

    // ---- pred rows straight into registers (LDG.128, all-or-nothing) ----
    F2x2 c[R];
    {
        float4 vT = ldrow(pred, gy0 + w * R, gxB);                 // my top halo row
        float4 vB = ldrow(pred, gy0 + 1 + (w + 1) * R, gxB);       // my bottom halo row
        #pragma unroll
        for (int r = 0; r < R; ++r) {
            float4 v = ldrow(pred, gy0 + 1 + w * R + r, gxB);
            c[r].a = pk2(v.x, v.y); c[r].b = pk2(v.z, v.w);
        }
        // ---- INIT edge slot (parity 2): inter-warp boundary rows of pred_0 ----
        {   // my last owned row is (w+1)'s top edge; slot 16 is a harmless sink
            float u0, u1, u2, u3;
            up2(c[R - 1].a, u0, u1); up2(c[R - 1].b, u2, u3);
            st4s(eT + (2 * ETSLOT + (w + 1)) * EXTX + col0,
                 make_float4(u0, u1, u2, u3));
            if (w > 0) {   // my first owned row is (w-1)'s bottom edge
                up2(c[0].a, u0, u1); up2(c[0].b, u2, u3);
                st4s(eB + (2 * WARPS + (w - 1)) * EXTX + col0,
                     make_float4(u0, u1, u2, u3));
            }
        }
        // ---- constant block-edge rows (pred_0 rows 0 / EXTY-1): all parities ----
        if (w == 0) {
            st4s(eT + (0 * ETSLOT + 0) * EXTX + col0, vT);
            st4s(eT + (1 * ETSLOT + 0) * EXTX + col0, vT);
            st4s(eT + (2 * ETSLOT + 0) * EXTX + col0, vT);
        }
        if (w == WARPS - 1) {
            st4s(eB + (0 * WARPS + WARPS - 1) * EXTX + col0, vB);
            st4s(eB + (1 * WARPS + WARPS - 1) * EXTX + col0, vB);
            st4s(eB + (2 * WARPS + WARPS - 1) * EXTX + col0, vB);
        }
    }

    // ---- gt: vectorized load, store gt/2, central sum ----
    float gtLocal = 0.f;
    #pragma unroll 1
    for (int i = tid; i < GTN / 4; i += NT) {
        int r  = i >> 5;             // 32 float4 per row
        int c4 = (i & 31) << 2;
        float4 v = ldrow(gt, gy0 + r, gx0 + c4);
        float4 h; h.x = 0.5f * v.x; h.y = 0.5f * v.y; h.z = 0.5f * v.z; h.w = 0.5f * v.w;
        *reinterpret_cast<float4*>(gtb + r * EXTX + c4) = h;
        if (r >= CLOY && r < CHIY && c4 >= CLOX && c4 < CHIX)
            gtLocal += (v.x + v.y) + (v.z + v.w);
    }
    __syncthreads();

    const bool colIn = (col0 >= CLOX) && (col0 < CHIX);   // whole-quad in/out
    const ull K10  = pk2(10.f, 10.f);
    const ull KN10 = pk2(-10.f, -10.f);
    const ull KN5  = pk2(-5.f, -5.f);

    float fnTotal = 0.f;

    #pragma unroll 1
    for (int k = 0; k < 5; ++k) {
        const int p = (k == 0) ? 2 : ((k - 1) & 1);   // read slot (2 = INIT)
        const float* eTr = eT + (p * ETSLOT + w) * EXTX + col0;
        const float* eBr = eB + (p * WARPS  + w) * EXTX + col0;

        F2x2 cT;
        {
            float4 v = ld4s(eTr);
            cT.a = pk2(v.x, v.y); cT.b = pk2(v.z, v.w);
        }
        F2x2 hP = hsum2(cT);
        F2x2 cC = c[0];
        F2x2 hC = hsum2(cC);
        ull acc = pk2(0.f, 0.f);
        const int  pw    = k & 1;
        const bool doUpd = (k < 4);

        #pragma unroll
        for (int r = 0; r < R; ++r) {
            const int y = 1 + w * R + r;
            F2x2 cN;
            if (r < R - 1) cN = c[r + 1];
            else {
                float4 v = ld4s(eBr);
                cN.a = pk2(v.x, v.y); cN.b = pk2(v.z, v.w);
            }
            F2x2 hN = hsum2(cN);

            ull sA = add2(add2(hP.a, hC.a), hN.a);     // unsat vertical sum
            ull sB = add2(add2(hP.b, hC.b), hN.b);
            ull mA = fma2(cC.a, KN10, KN5);            // -10c - 5
            ull mB = fma2(cC.b, KN10, KN5);
            ull a1A = fma2(sA, K10, mA);               // 10s + m
            ull a1B = fma2(sB, K10, mB);
            ull a2A = add2(mA, K10);                   // 10 + m  (clip at d=1)
            ull a2B = add2(mB, K10);

            float p0, p1, p2, p3, q0, q1, q2, q3;
            up2(a1A, p0, p1); up2(a1B, p2, p3);
            up2(a2A, q0, q1); up2(a2B, q2, q3);
            ull thA = pk2(tanha(fminf(p0, q0)), tanha(fminf(p1, q1)));
            ull thB = pk2(tanha(fminf(p2, q2)), tanha(fminf(p3, q3)));

            float4 g4 = ld4s(gtb + y * EXTX + col0);
            ull gA = pk2(g4.x, g4.y), gB = pk2(g4.z, g4.w);
            ull fnA = fma2(gA, thA, gA);               // gt * sigmoid
            ull fnB = fma2(gB, thB, gB);

            if (doUpd) {
                F2x2 np;
                np.a = add2(cC.a, fnA);
                np.b = add2(cC.b, fnB);
                c[r] = np;
                if (r == 0 && w > 0) {
                    ull* e = reinterpret_cast<ull*>(eB + (pw * WARPS + (w - 1)) * EXTX + col0);
                    e[0] = np.a; e[1] = np.b;
                }
                if (r == R - 1) {
                    ull* e = reinterpret_cast<ull*>(eT + (pw * ETSLOT + (w + 1)) * EXTX + col0);
                    e[0] = np.a; e[1] = np.b;
                }
            }

            if (colIn && y >= CLOY && y < CHIY)
                acc = add2(acc, add2(fnA, fnB));

            hP = hC; hC = hN; cC = cN;
        }

        const float wk = (float)((k + 1) * (k + 1));
        float u0, u1;
        up2(acc, u0, u1);
        fnTotal = fmaf(wk, u0 + u1, fnTotal);
        if (k < 4) __syncthreads();
    }

    // ---- block reduction -> global atomics, last block finalizes ----
    #pragma unroll
    for (int o = 16; o; o >>= 1) {
        fnTotal += __shfl_down_sync(0xffffffffu, fnTotal, o);
        gtLocal += __shfl_down_sync(0xffffffffu, gtLocal, o);
    }
    __shared__ float red[WARPS][2];
    if (lane == 0) { red[w][0] = fnTotal; red[w][1] = gtLocal; }
    __syncthreads();
    if (tid < 32) {
        fnTotal = (tid < WARPS) ? red[tid][0] : 0.f;
        gtLocal = (tid < WARPS) ? red[tid][1] : 0.f;
        #pragma unroll
        for (int o = 8; o; o >>= 1) {
            fnTotal += __shfl_down_sync(0xffffffffu, fnTotal, o);
            gtLocal += __shfl_down_sync(0xffffffffu, gtLocal, o);
        }
        if (tid == 0) {
            atomicAdd(&g_acc[0], fnTotal);
            atomicAdd(&g_acc[1], gtLocal);
            __threadfence();
            unsigned prev = atomicAdd(&g_done, 1u);
            if (prev == NBLK - 1) {
                out[0] = g_acc[0] / g_acc[1];
                g_acc[0] = 0.f;
                g_acc[1] = 0.f;
                __threadfence();
                g_done = 0u;
            }
        }
    }
}

extern "C" void kernel_launch(void* const* d_in, const int* in_sizes, int n_in,
                              void* d_out, int out_size)
{
    const float* pred = (const float*)d_in[0];
    const float* gt   = (const float*)d_in[1];

    cudaFuncSetAttribute(wlc_main, cudaFuncAttributeMaxDynamicSharedMemorySize,
                         SMEMB);

    dim3 grid(GRIDX, GRIDY);     // 37 x 40 = 1480 blocks
    wlc_main<<<grid, NT, SMEMB>>>(pred, gt, (float*)d_out);
}